// round 7
// baseline (speedup 1.0000x reference)
#include <cuda_runtime.h>
#include <cuda_bf16.h>

// ---------------------------------------------------------------------------
// Fused LEMURS actor, round 7:
//  - 5 blocks/SM (51-reg cap, 40KB smem via buffer aliasing) -> 62.5% occ
//  - attention at 4.0 instr/exp: separate k/v arrays, LDS.128 quad loads,
//    f32x2 num+den accumulation (den via packed-ones multiplier)
//  - pre-packed duplicated weights (float4 qkqk / float2 vv): no pack MOVs
//  - q prescaled into smem, attention r-loops rolled (low reg pressure)
// ---------------------------------------------------------------------------

#define RPB 16
#define NTHREADS 256

typedef unsigned long long u64;

// Pre-packed transposed weights
__device__ float  g_WinT[12 * 128];
__device__ float4 g_Wqk1[128 * 128];   // (wq,wq,wk,wk) [j][i]
__device__ float2 g_Wv1[128 * 128];    // (wv,wv)
__device__ float2 g_Wh2[128 * 64];     // (w,w)
__device__ float4 g_Wqk2[64 * 64];
__device__ float2 g_Wv2[64 * 64];

__device__ __forceinline__ u64 pack2(float a, float b) {
    u64 r;
    asm("mov.b64 %0, {%1, %2};" : "=l"(r) : "f"(a), "f"(b));
    return r;
}
__device__ __forceinline__ void ffma2(u64& d, u64 a, u64 b) {
    asm("fma.rn.f32x2 %0, %1, %2, %0;" : "+l"(d) : "l"(a), "l"(b));
}
__device__ __forceinline__ float2 unpack2(u64 v) {
    float2 f;
    asm("mov.b64 {%0, %1}, %2;" : "=f"(f.x), "=f"(f.y) : "l"(v));
    return f;
}
__device__ __forceinline__ float ex2f(float x) {
    float y;
    asm("ex2.approx.ftz.f32 %0, %1;" : "=f"(y) : "f"(x));
    return y;
}
__device__ __forceinline__ float siluf(float v) {
    return __fdividef(v, 1.0f + __expf(-v));
}

__global__ void prep_weights(const float* __restrict__ Win,
                             const float* __restrict__ Aq1,
                             const float* __restrict__ Ak1,
                             const float* __restrict__ Av1,
                             const float* __restrict__ Wh,
                             const float* __restrict__ Aq2,
                             const float* __restrict__ Ak2,
                             const float* __restrict__ Av2) {
    int t = blockIdx.x * blockDim.x + threadIdx.x;
    int stride = gridDim.x * blockDim.x;
    for (int idx = t; idx < 128 * 12; idx += stride) {
        int i = idx / 12, j = idx - i * 12;
        g_WinT[j * 128 + i] = Win[idx];
    }
    for (int idx = t; idx < 128 * 128; idx += stride) {
        int i = idx >> 7, j = idx & 127;
        float wq = Aq1[idx], wk = Ak1[idx], wv = Av1[idx];
        g_Wqk1[j * 128 + i] = make_float4(wq, wq, wk, wk);
        g_Wv1[j * 128 + i]  = make_float2(wv, wv);
    }
    for (int idx = t; idx < 64 * 128; idx += stride) {
        int i = idx >> 7, j = idx & 127;
        float w = Wh[idx];
        g_Wh2[j * 64 + i] = make_float2(w, w);
    }
    for (int idx = t; idx < 64 * 64; idx += stride) {
        int i = idx >> 6, j = idx & 63;
        float wq = Aq2[idx], wk = Ak2[idx], wv = Av2[idx];
        g_Wqk2[j * 64 + i] = make_float4(wq, wq, wk, wk);
        g_Wv2[j * 64 + i]  = make_float2(wv, wv);
    }
}

__global__ __launch_bounds__(NTHREADS, 5)
void lemurs_fused(const float* __restrict__ x,
                  const float* __restrict__ b_in,
                  const float* __restrict__ Bq1, const float* __restrict__ Bk1,
                  const float* __restrict__ Bv1,
                  const float* __restrict__ b_h,
                  const float* __restrict__ Bq2, const float* __restrict__ Bk2,
                  const float* __restrict__ Bv2,
                  const float* __restrict__ Wout,
                  const float* __restrict__ b_out,
                  float* __restrict__ out) {
    // ~40KB total; attn2 buffers alias attn1 buffers
    __shared__ __align__(16) float shT[128 * 20];   // h1 -> attn1out; [0..1024) also attn2out, [1024..1424) y
    __shared__ __align__(16) float sk[RPB * 128];   // k1; first 1024: k2
    __shared__ __align__(16) float sv[RPB * 128];   // v1; first 1024: v2
    __shared__ __align__(16) float sqs[RPB * 128];  // q1'; first 1024: q2'
    __shared__ __align__(16) float sh2T[64 * 20];   // h2
    __shared__ __align__(16) float sx[RPB * 12];

    const int t = threadIdx.x;
    const int row0 = blockIdx.x * RPB;
    const float LOG2E = 1.4426950408889634f;

    if (t < RPB * 12) sx[t] = x[row0 * 12 + t];
    __syncthreads();

    const int i  = t & 127;
    const int g  = t >> 7;   // 0/1
    const int i2 = t & 63;
    const int g4 = t >> 6;   // 0..3

    // ---- phase 1: h1 = silu(x @ W_in^T + b_in) -> shT[feat*20 + row] ----
    {
        float acc[8];
        float bb = b_in[i];
#pragma unroll
        for (int r = 0; r < 8; r++) acc[r] = bb;
#pragma unroll
        for (int j = 0; j < 12; j++) {
            float w = g_WinT[j * 128 + i];
#pragma unroll
            for (int r = 0; r < 8; r++)
                acc[r] += w * sx[(g * 8 + r) * 12 + j];
        }
        float4 o0 = make_float4(siluf(acc[0]), siluf(acc[1]),
                                siluf(acc[2]), siluf(acc[3]));
        float4 o1 = make_float4(siluf(acc[4]), siluf(acc[5]),
                                siluf(acc[6]), siluf(acc[7]));
        *(float4*)&shT[i * 20 + g * 8]     = o0;
        *(float4*)&shT[i * 20 + g * 8 + 4] = o1;
    }
    __syncthreads();

    // ---- phase 2: q1,k1,v1 (128x128 GEMMs, f32x2, pre-packed weights) ----
    {
        u64 aq[4], ak[4], av[4];
        {
            float bq = Bq1[i], bk = Bk1[i], bv = Bv1[i];
            u64 bq2 = pack2(bq, bq), bk2 = pack2(bk, bk), bv2 = pack2(bv, bv);
#pragma unroll
            for (int p = 0; p < 4; p++) { aq[p] = bq2; ak[p] = bk2; av[p] = bv2; }
        }
        const ulonglong2* Wqk = (const ulonglong2*)g_Wqk1;
        const u64* Wv = (const u64*)g_Wv1;
#pragma unroll 2
        for (int j = 0; j < 128; j++) {
            ulonglong2 wqk = Wqk[j * 128 + i];
            u64 wv2 = Wv[j * 128 + i];
            ulonglong2 ha = *(const ulonglong2*)&shT[j * 20 + g * 8];
            ulonglong2 hb = *(const ulonglong2*)&shT[j * 20 + g * 8 + 4];
            ffma2(aq[0], wqk.x, ha.x); ffma2(aq[1], wqk.x, ha.y);
            ffma2(aq[2], wqk.x, hb.x); ffma2(aq[3], wqk.x, hb.y);
            ffma2(ak[0], wqk.y, ha.x); ffma2(ak[1], wqk.y, ha.y);
            ffma2(ak[2], wqk.y, hb.x); ffma2(ak[3], wqk.y, hb.y);
            ffma2(av[0], wv2, ha.x);   ffma2(av[1], wv2, ha.y);
            ffma2(av[2], wv2, hb.x);   ffma2(av[3], wv2, hb.y);
        }
#pragma unroll
        for (int p = 0; p < 4; p++) {
            float2 fq = unpack2(aq[p]);
            float2 fk = unpack2(ak[p]);
            float2 fv = unpack2(av[p]);
            int r0 = g * 8 + 2 * p;
            sqs[r0 * 128 + i]       = siluf(fq.x) * LOG2E;
            sqs[(r0 + 1) * 128 + i] = siluf(fq.y) * LOG2E;
            sk[r0 * 128 + i]        = siluf(fk.x);
            sk[(r0 + 1) * 128 + i]  = siluf(fk.y);
            sv[r0 * 128 + i]        = siluf(fv.x);
            sv[(r0 + 1) * 128 + i]  = siluf(fv.y);
        }
    }
    __syncthreads();

    // ---- phase 3: attention 1 (4.0 instr/exp) ----
    {
        const u64 ONE2 = pack2(1.0f, 1.0f);
        const u64 ZERO2 = pack2(0.0f, 0.0f);
        for (int r = 0; r < 8; r++) {
            int row = g * 8 + r;
            float qv = sqs[row * 128 + i];
            const float4* k4 = (const float4*)&sk[row * 128];
            const ulonglong2* v4 = (const ulonglong2*)&sv[row * 128];
            u64 n01 = ZERO2, n23 = ZERO2, d01 = ZERO2, d23 = ZERO2;
#pragma unroll 4
            for (int jj = 0; jj < 32; jj++) {
                float4 kk = k4[jj];
                ulonglong2 vv = v4[jj];
                float e0 = ex2f(qv * kk.x);
                float e1 = ex2f(qv * kk.y);
                float e2 = ex2f(qv * kk.z);
                float e3 = ex2f(qv * kk.w);
                u64 e01 = pack2(e0, e1), e23 = pack2(e2, e3);
                ffma2(n01, e01, vv.x); ffma2(n23, e23, vv.y);
                ffma2(d01, e01, ONE2); ffma2(d23, e23, ONE2);
            }
            float2 a = unpack2(n01), b = unpack2(n23);
            float2 c = unpack2(d01), d = unpack2(d23);
            float num = (a.x + a.y) + (b.x + b.y);
            float den = (c.x + c.y) + (d.x + d.y);
            shT[i * 20 + row] = siluf(__fdividef(num, den));
        }
    }
    __syncthreads();

    // ---- phase 4: h2 = silu(attn1 @ W_h^T + b_h) -> sh2T ----
    {
        u64 a2[2];
        float bb = b_h[i2];
        a2[0] = a2[1] = pack2(bb, bb);
        const u64* Wh = (const u64*)g_Wh2;
#pragma unroll 4
        for (int j = 0; j < 128; j++) {
            u64 w2 = Wh[j * 64 + i2];
            ulonglong2 hv = *(const ulonglong2*)&shT[j * 20 + g4 * 4];
            ffma2(a2[0], w2, hv.x);
            ffma2(a2[1], w2, hv.y);
        }
        float2 f0 = unpack2(a2[0]), f1 = unpack2(a2[1]);
        float4 o = make_float4(siluf(f0.x), siluf(f0.y),
                               siluf(f1.x), siluf(f1.y));
        *(float4*)&sh2T[i2 * 20 + g4 * 4] = o;
    }
    __syncthreads();

    // ---- phase 5: q2,k2,v2 (64x64 GEMMs) ----
    {
        u64 aq[2], ak[2], av[2];
        {
            float bq = Bq2[i2], bk = Bk2[i2], bv = Bv2[i2];
            aq[0] = aq[1] = pack2(bq, bq);
            ak[0] = ak[1] = pack2(bk, bk);
            av[0] = av[1] = pack2(bv, bv);
        }
        const ulonglong2* Wqk = (const ulonglong2*)g_Wqk2;
        const u64* Wv = (const u64*)g_Wv2;
#pragma unroll 2
        for (int j = 0; j < 64; j++) {
            ulonglong2 wqk = Wqk[j * 64 + i2];
            u64 wv2 = Wv[j * 64 + i2];
            ulonglong2 hv = *(const ulonglong2*)&sh2T[j * 20 + g4 * 4];
            ffma2(aq[0], wqk.x, hv.x); ffma2(aq[1], wqk.x, hv.y);
            ffma2(ak[0], wqk.y, hv.x); ffma2(ak[1], wqk.y, hv.y);
            ffma2(av[0], wv2, hv.x);   ffma2(av[1], wv2, hv.y);
        }
#pragma unroll
        for (int p = 0; p < 2; p++) {
            float2 fq = unpack2(aq[p]);
            float2 fk = unpack2(ak[p]);
            float2 fv = unpack2(av[p]);
            int r0 = g4 * 4 + 2 * p;
            sqs[r0 * 64 + i2]       = siluf(fq.x) * LOG2E;
            sqs[(r0 + 1) * 64 + i2] = siluf(fq.y) * LOG2E;
            sk[r0 * 64 + i2]        = siluf(fk.x);
            sk[(r0 + 1) * 64 + i2]  = siluf(fk.y);
            sv[r0 * 64 + i2]        = siluf(fv.x);
            sv[(r0 + 1) * 64 + i2]  = siluf(fv.y);
        }
    }
    __syncthreads();

    // ---- phase 6: attention 2 ----
    {
        const u64 ONE2 = pack2(1.0f, 1.0f);
        const u64 ZERO2 = pack2(0.0f, 0.0f);
        for (int r = 0; r < 4; r++) {
            int row = g4 * 4 + r;
            float qv = sqs[row * 64 + i2];
            const float4* k4 = (const float4*)&sk[row * 64];
            const ulonglong2* v4 = (const ulonglong2*)&sv[row * 64];
            u64 n01 = ZERO2, n23 = ZERO2, d01 = ZERO2, d23 = ZERO2;
#pragma unroll 4
            for (int jj = 0; jj < 16; jj++) {
                float4 kk = k4[jj];
                ulonglong2 vv = v4[jj];
                float e0 = ex2f(qv * kk.x);
                float e1 = ex2f(qv * kk.y);
                float e2 = ex2f(qv * kk.z);
                float e3 = ex2f(qv * kk.w);
                u64 e01 = pack2(e0, e1), e23 = pack2(e2, e3);
                ffma2(n01, e01, vv.x); ffma2(n23, e23, vv.y);
                ffma2(d01, e01, ONE2); ffma2(d23, e23, ONE2);
            }
            float2 a = unpack2(n01), b = unpack2(n23);
            float2 c = unpack2(d01), d = unpack2(d23);
            float num = (a.x + a.y) + (b.x + b.y);
            float den = (c.x + c.y) + (d.x + d.y);
            // attn2 out -> shT[0..1024)
            shT[row * 64 + i2] = siluf(__fdividef(num, den));
        }
    }
    __syncthreads();

    // ---- phase 7: y = silu(attn2 @ W_out^T + b_out) -> shT[1024..1424) ----
    for (int idx = t; idx < RPB * 25; idx += NTHREADS) {
        int r = idx / 25;
        int o = idx - r * 25;
        float acc = b_out[o];
        const float4* wrow = (const float4*)&Wout[o * 64];
        const float4* arow = (const float4*)&shT[r * 64];
#pragma unroll
        for (int j = 0; j < 16; j++) {
            float4 w = wrow[j];
            float4 a = arow[j];
            acc += w.x * a.x + w.y * a.y + w.z * a.z + w.w * a.w;
        }
        shT[1024 + idx] = siluf(acc);
    }
    __syncthreads();

    // ---- phase 8: quadratic-form reduction ----
    if (t < RPB) {
        const float* y = &shT[1024 + t * 25];
        float M11 = 0.f, M12 = 0.f, M21 = 0.f, M22 = 0.f, Mpp = 0.f;
#pragma unroll
        for (int j = 0; j < 5; j++) {
            M11 += y[j] * y[j];
            M12 += y[5 + j] * y[5 + j];
            M21 += y[10 + j] * y[10 + j];
            M22 += y[15 + j] * y[15 + j];
            Mpp += y[20 + j] * y[20 + j];
        }
        float q0 = y[0], q1 = y[1], qq2 = y[2], q3 = y[3];
        float quad = M11 * (q0 * q0 + q1 * q1)
                   + (M12 + M21) * (q0 * qq2 + q1 * q3)
                   + M22 * (qq2 * qq2 + q3 * q3);
        out[row0 + t] = quad + Mpp;
    }
}

extern "C" void kernel_launch(void* const* d_in, const int* in_sizes, int n_in,
                              void* d_out, int out_size) {
    const float* x     = (const float*)d_in[0];
    const float* W_in  = (const float*)d_in[2];
    const float* b_in  = (const float*)d_in[3];
    const float* Aq4   = (const float*)d_in[4];
    const float* Bq4   = (const float*)d_in[5];
    const float* Ak4   = (const float*)d_in[6];
    const float* Bk4   = (const float*)d_in[7];
    const float* Av4   = (const float*)d_in[8];
    const float* Bv4   = (const float*)d_in[9];
    const float* W_h   = (const float*)d_in[10];
    const float* b_h   = (const float*)d_in[11];
    const float* Aq7   = (const float*)d_in[12];
    const float* Bq7   = (const float*)d_in[13];
    const float* Ak7   = (const float*)d_in[14];
    const float* Bk7   = (const float*)d_in[15];
    const float* Av7   = (const float*)d_in[16];
    const float* Bv7   = (const float*)d_in[17];
    const float* W_out = (const float*)d_in[18];
    const float* b_out = (const float*)d_in[19];

    int nrows = in_sizes[0] / 12;

    prep_weights<<<128, 256>>>(W_in, Aq4, Ak4, Av4, W_h, Aq7, Ak7, Av7);
    lemurs_fused<<<nrows / RPB, NTHREADS>>>(x, b_in, Bq4, Bk4, Bv4,
                                            b_h, Bq7, Bk7, Bv7,
                                            W_out, b_out, (float*)d_out);
}

// round 8
// speedup vs baseline: 1.1927x; 1.1927x over previous
#include <cuda_runtime.h>
#include <cuda_bf16.h>

// ---------------------------------------------------------------------------
// Fused LEMURS actor, round 8:
//  - R6 structure (q in regs, unrolled attention rows, scalar weight loads,
//    interleaved (k,v) float2) -- the 152us baseline
//  - 128-thread blocks, RPB=8, 8 blocks/SM: 8 independent phase streams/SM
//    so attention (MUFU-bound) of some blocks overlaps GEMM (FMA-bound) of
//    others; cheaper barriers
// ---------------------------------------------------------------------------

#define RPB 8
#define NTHREADS 128

typedef unsigned long long u64;

// Transposed weights (column-major: per-j loads broadcast-friendly)
__device__ float g_WinT[12 * 128];
__device__ float g_AqT1[128 * 128];
__device__ float g_AkT1[128 * 128];
__device__ float g_AvT1[128 * 128];
__device__ float g_WhT[128 * 64];
__device__ float g_AqT2[64 * 64];
__device__ float g_AkT2[64 * 64];
__device__ float g_AvT2[64 * 64];

__device__ __forceinline__ u64 pack2(float a, float b) {
    u64 r;
    asm("mov.b64 %0, {%1, %2};" : "=l"(r) : "f"(a), "f"(b));
    return r;
}
__device__ __forceinline__ void ffma2(u64& d, u64 a, u64 b) {
    asm("fma.rn.f32x2 %0, %1, %2, %0;" : "+l"(d) : "l"(a), "l"(b));
}
__device__ __forceinline__ float2 unpack2(u64 v) {
    float2 f;
    asm("mov.b64 {%0, %1}, %2;" : "=f"(f.x), "=f"(f.y) : "l"(v));
    return f;
}
__device__ __forceinline__ float ex2f(float x) {
    float y;
    asm("ex2.approx.ftz.f32 %0, %1;" : "=f"(y) : "f"(x));
    return y;
}
__device__ __forceinline__ float siluf(float v) {
    return __fdividef(v, 1.0f + __expf(-v));
}

__global__ void prep_weights(const float* __restrict__ Win,
                             const float* __restrict__ Aq1,
                             const float* __restrict__ Ak1,
                             const float* __restrict__ Av1,
                             const float* __restrict__ Wh,
                             const float* __restrict__ Aq2,
                             const float* __restrict__ Ak2,
                             const float* __restrict__ Av2) {
    int t = blockIdx.x * blockDim.x + threadIdx.x;
    int stride = gridDim.x * blockDim.x;
    for (int idx = t; idx < 128 * 12; idx += stride) {
        int i = idx / 12, j = idx - i * 12;
        g_WinT[j * 128 + i] = Win[idx];
    }
    for (int idx = t; idx < 128 * 128; idx += stride) {
        int i = idx >> 7, j = idx & 127;
        g_AqT1[j * 128 + i] = Aq1[idx];
        g_AkT1[j * 128 + i] = Ak1[idx];
        g_AvT1[j * 128 + i] = Av1[idx];
    }
    for (int idx = t; idx < 64 * 128; idx += stride) {
        int i = idx >> 7, j = idx & 127;
        g_WhT[j * 64 + i] = Wh[idx];
    }
    for (int idx = t; idx < 64 * 64; idx += stride) {
        int i = idx >> 6, j = idx & 63;
        g_AqT2[j * 64 + i] = Aq2[idx];
        g_AkT2[j * 64 + i] = Ak2[idx];
        g_AvT2[j * 64 + i] = Av2[idx];
    }
}

// feature-major stride: 8 rows + 4 pad = 12 (16B-aligned row groups)
#define HSTR 12

__global__ __launch_bounds__(NTHREADS, 8)
void lemurs_fused(const float* __restrict__ x,
                  const float* __restrict__ b_in,
                  const float* __restrict__ Bq1, const float* __restrict__ Bk1,
                  const float* __restrict__ Bv1,
                  const float* __restrict__ b_h,
                  const float* __restrict__ Bq2, const float* __restrict__ Bk2,
                  const float* __restrict__ Bv2,
                  const float* __restrict__ Wout,
                  const float* __restrict__ b_out,
                  float* __restrict__ out) {
    __shared__ __align__(16) float sx[RPB * 12];          //  384 B
    __shared__ __align__(16) float shT[128 * HSTR];       //  6 KB  h1 -> attn1out
    __shared__ __align__(16) float skv[RPB * 128 * 2];    //  8 KB  (k,v) attn1/2
    __shared__ __align__(16) float sh2T[64 * HSTR];       //  3 KB  h2
    __shared__ __align__(16) float sAt2[RPB * 64];        //  2 KB  attn2 out
    __shared__ float sy[RPB * 25];                        //  800 B

    const int t = threadIdx.x;
    const int row0 = blockIdx.x * RPB;
    const float LOG2E = 1.4426950408889634f;

    if (t < RPB * 12) sx[t] = x[row0 * 12 + t];
    __syncthreads();

    const int i  = t;        // feature (128-wide phases), 0..127
    const int i2 = t & 63;   // feature (64-wide phases)
    const int g4 = t >> 6;   // 0/1: 4-row half

    // ---- phase 1: h1 = silu(x @ W_in^T + b_in) -> shT[feat*HSTR + row] ----
    {
        float acc[8];
        float bb = b_in[i];
#pragma unroll
        for (int r = 0; r < 8; r++) acc[r] = bb;
#pragma unroll
        for (int j = 0; j < 12; j++) {
            float w = g_WinT[j * 128 + i];
#pragma unroll
            for (int r = 0; r < 8; r++)
                acc[r] += w * sx[r * 12 + j];
        }
        float4 o0 = make_float4(siluf(acc[0]), siluf(acc[1]),
                                siluf(acc[2]), siluf(acc[3]));
        float4 o1 = make_float4(siluf(acc[4]), siluf(acc[5]),
                                siluf(acc[6]), siluf(acc[7]));
        *(float4*)&shT[i * HSTR]     = o0;
        *(float4*)&shT[i * HSTR + 4] = o1;
    }
    __syncthreads();

    // ---- phase 2: q1,k1,v1 = silu(h1 @ A^T + B), f32x2 packed ----
    float q[8];  // prescaled q stays in registers through phase 3
    {
        u64 aq[4], ak[4], av[4];
        float bq = Bq1[i], bk = Bk1[i], bv = Bv1[i];
        u64 bq2 = pack2(bq, bq), bk2 = pack2(bk, bk), bv2 = pack2(bv, bv);
#pragma unroll
        for (int p = 0; p < 4; p++) { aq[p] = bq2; ak[p] = bk2; av[p] = bv2; }
#pragma unroll 4
        for (int j = 0; j < 128; j++) {
            float wq = g_AqT1[j * 128 + i];
            float wk = g_AkT1[j * 128 + i];
            float wv = g_AvT1[j * 128 + i];
            u64 wq2 = pack2(wq, wq), wk2 = pack2(wk, wk), wv2 = pack2(wv, wv);
            ulonglong2 ha = *(const ulonglong2*)&shT[j * HSTR];
            ulonglong2 hb = *(const ulonglong2*)&shT[j * HSTR + 4];
            ffma2(aq[0], wq2, ha.x); ffma2(aq[1], wq2, ha.y);
            ffma2(aq[2], wq2, hb.x); ffma2(aq[3], wq2, hb.y);
            ffma2(ak[0], wk2, ha.x); ffma2(ak[1], wk2, ha.y);
            ffma2(ak[2], wk2, hb.x); ffma2(ak[3], wk2, hb.y);
            ffma2(av[0], wv2, ha.x); ffma2(av[1], wv2, ha.y);
            ffma2(av[2], wv2, hb.x); ffma2(av[3], wv2, hb.y);
        }
        float2* kvp = (float2*)skv;
#pragma unroll
        for (int p = 0; p < 4; p++) {
            float2 fq = unpack2(aq[p]);
            float2 fk = unpack2(ak[p]);
            float2 fv = unpack2(av[p]);
            int r0 = 2 * p;
            q[r0]     = siluf(fq.x) * LOG2E;
            q[r0 + 1] = siluf(fq.y) * LOG2E;
            kvp[r0 * 128 + i]       = make_float2(siluf(fk.x), siluf(fv.x));
            kvp[(r0 + 1) * 128 + i] = make_float2(siluf(fk.y), siluf(fv.y));
        }
    }
    __syncthreads();

    // ---- phase 3: attention 1 (q in regs, kv broadcast from smem) ----
    {
#pragma unroll
        for (int r = 0; r < 8; r++) {
            float qv = q[r];
            const float2* kv = (const float2*)&skv[r * 256];
            float num = 0.f, den = 0.f;
#pragma unroll 8
            for (int j = 0; j < 128; j++) {
                float2 p = kv[j];
                float e = ex2f(qv * p.x);
                num += e * p.y;
                den += e;
            }
            shT[i * HSTR + r] = siluf(__fdividef(num, den));
        }
    }
    __syncthreads();

    // ---- phase 4: h2 = silu(attn1 @ W_h^T + b_h) -> sh2T ----
    {
        u64 a2[2];
        float bb = b_h[i2];
        a2[0] = a2[1] = pack2(bb, bb);
#pragma unroll 4
        for (int j = 0; j < 128; j++) {
            float w = g_WhT[j * 64 + i2];
            u64 w2 = pack2(w, w);
            ulonglong2 hv = *(const ulonglong2*)&shT[j * HSTR + g4 * 4];
            ffma2(a2[0], w2, hv.x);
            ffma2(a2[1], w2, hv.y);
        }
        float2 f0 = unpack2(a2[0]), f1 = unpack2(a2[1]);
        float4 o = make_float4(siluf(f0.x), siluf(f0.y),
                               siluf(f1.x), siluf(f1.y));
        *(float4*)&sh2T[i2 * HSTR + g4 * 4] = o;
    }
    __syncthreads();

    // ---- phase 5: q2,k2,v2 GEMMs (64x64), f32x2 packed ----
    float q2[4];
    {
        u64 aq[2], ak[2], av[2];
        float bq = Bq2[i2], bk = Bk2[i2], bv = Bv2[i2];
        aq[0] = aq[1] = pack2(bq, bq);
        ak[0] = ak[1] = pack2(bk, bk);
        av[0] = av[1] = pack2(bv, bv);
#pragma unroll 4
        for (int j = 0; j < 64; j++) {
            float wq = g_AqT2[j * 64 + i2];
            float wk = g_AkT2[j * 64 + i2];
            float wv = g_AvT2[j * 64 + i2];
            u64 wq2 = pack2(wq, wq), wk2 = pack2(wk, wk), wv2 = pack2(wv, wv);
            ulonglong2 hv = *(const ulonglong2*)&sh2T[j * HSTR + g4 * 4];
            ffma2(aq[0], wq2, hv.x); ffma2(aq[1], wq2, hv.y);
            ffma2(ak[0], wk2, hv.x); ffma2(ak[1], wk2, hv.y);
            ffma2(av[0], wv2, hv.x); ffma2(av[1], wv2, hv.y);
        }
        float2* kvp = (float2*)skv;
#pragma unroll
        for (int p = 0; p < 2; p++) {
            float2 fq = unpack2(aq[p]);
            float2 fk = unpack2(ak[p]);
            float2 fv = unpack2(av[p]);
            int r0 = g4 * 4 + 2 * p;
            q2[2 * p]     = siluf(fq.x) * LOG2E;
            q2[2 * p + 1] = siluf(fq.y) * LOG2E;
            kvp[r0 * 64 + i2]       = make_float2(siluf(fk.x), siluf(fv.x));
            kvp[(r0 + 1) * 64 + i2] = make_float2(siluf(fk.y), siluf(fv.y));
        }
    }
    __syncthreads();

    // ---- phase 6: attention 2 ----
    {
#pragma unroll
        for (int r = 0; r < 4; r++) {
            int row = g4 * 4 + r;
            float qv = q2[r];
            const float2* kv = (const float2*)&skv[row * 128];
            float num = 0.f, den = 0.f;
#pragma unroll 8
            for (int j = 0; j < 64; j++) {
                float2 p = kv[j];
                float e = ex2f(qv * p.x);
                num += e * p.y;
                den += e;
            }
            sAt2[row * 64 + i2] = siluf(__fdividef(num, den));
        }
    }
    __syncthreads();

    // ---- phase 7: y = silu(attn2 @ W_out^T + b_out) ----
    for (int idx = t; idx < RPB * 25; idx += NTHREADS) {
        int r = idx / 25;
        int o = idx - r * 25;
        float acc = b_out[o];
        const float4* wrow = (const float4*)&Wout[o * 64];
        const float4* arow = (const float4*)&sAt2[r * 64];
#pragma unroll
        for (int j = 0; j < 16; j++) {
            float4 w = wrow[j];
            float4 a = arow[j];
            acc += w.x * a.x + w.y * a.y + w.z * a.z + w.w * a.w;
        }
        sy[idx] = siluf(acc);
    }
    __syncthreads();

    // ---- phase 8: quadratic-form reduction ----
    if (t < RPB) {
        const float* y = &sy[t * 25];
        float M11 = 0.f, M12 = 0.f, M21 = 0.f, M22 = 0.f, Mpp = 0.f;
#pragma unroll
        for (int j = 0; j < 5; j++) {
            M11 += y[j] * y[j];
            M12 += y[5 + j] * y[5 + j];
            M21 += y[10 + j] * y[10 + j];
            M22 += y[15 + j] * y[15 + j];
            Mpp += y[20 + j] * y[20 + j];
        }
        float q0 = y[0], q1 = y[1], qq2 = y[2], q3 = y[3];
        float quad = M11 * (q0 * q0 + q1 * q1)
                   + (M12 + M21) * (q0 * qq2 + q1 * q3)
                   + M22 * (qq2 * qq2 + q3 * q3);
        out[row0 + t] = quad + Mpp;
    }
}

extern "C" void kernel_launch(void* const* d_in, const int* in_sizes, int n_in,
                              void* d_out, int out_size) {
    const float* x     = (const float*)d_in[0];
    const float* W_in  = (const float*)d_in[2];
    const float* b_in  = (const float*)d_in[3];
    const float* Aq4   = (const float*)d_in[4];
    const float* Bq4   = (const float*)d_in[5];
    const float* Ak4   = (const float*)d_in[6];
    const float* Bk4   = (const float*)d_in[7];
    const float* Av4   = (const float*)d_in[8];
    const float* Bv4   = (const float*)d_in[9];
    const float* W_h   = (const float*)d_in[10];
    const float* b_h   = (const float*)d_in[11];
    const float* Aq7   = (const float*)d_in[12];
    const float* Bq7   = (const float*)d_in[13];
    const float* Ak7   = (const float*)d_in[14];
    const float* Bk7   = (const float*)d_in[15];
    const float* Av7   = (const float*)d_in[16];
    const float* Bv7   = (const float*)d_in[17];
    const float* W_out = (const float*)d_in[18];
    const float* b_out = (const float*)d_in[19];

    int nrows = in_sizes[0] / 12;

    prep_weights<<<64, 256>>>(W_in, Aq4, Ak4, Av4, W_h, Aq7, Ak7, Av7);
    lemurs_fused<<<nrows / RPB, NTHREADS>>>(x, b_in, Bq4, Bk4, Bv4,
                                            b_h, Bq7, Bk7, Bv7,
                                            W_out, b_out, (float*)d_out);
}